// round 16
// baseline (speedup 1.0000x reference)
#include <cuda_runtime.h>
#include <cuda_fp16.h>
#include <math.h>

#define BB 16
#define LL 512
#define DD 768
#define HOPS 3
#define NH (HOPS + 1)

// ---------------- scratch (static device globals; no allocs) ----------------
__device__ __align__(16) __half g_inrH[(long)BB * LL * DD];     // inputs fp16, token-major
__device__ __align__(16) __half g_convrH0[(long)BB * LL * DD];  // conv fp16 (ping)
__device__ __align__(16) __half g_convrH1[(long)BB * LL * DD];  // conv fp16 (pong)
__device__ __align__(16) float  g_scores[(long)BB * LL * LL];   // scores partial (K half 0)
__device__ __align__(16) float  g_scores2[(long)BB * LL * LL];  // scores partial (K half 1)
__device__ __align__(16) float  g_convP[2L * BB * LL * DD];     // conv split-K fp32 partials
__device__ __align__(16) __half g_scoresH[(long)BB * LL * LL];  // post-softmax fp16
__device__ __align__(16) __half g_resultrH[(long)BB * LL * NH * DD]; // [B,L,4,D] fp16
__device__ __align__(16) __half g_wtH[(long)HOPS * DD * 3 * DD];     // conv W [h][o][k] K-major
__device__ __align__(16) __half g_w1T[(long)DD * DD];                // pool W1^T [e][d]
__device__ __align__(16) float  g_pp[(long)BB * LL * NH * 24];       // pool-score partials
__device__ __align__(16) float  g_invn[(long)BB * LL];               // 1/||conv row||

// ---------------- mma m16n8k16 fp16 -> fp32 ---------------------------------
__device__ __forceinline__ void mma_f16(float c[4],
                                        unsigned a0, unsigned a1, unsigned a2, unsigned a3,
                                        unsigned b0, unsigned b1) {
    asm volatile(
        "mma.sync.aligned.m16n8k16.row.col.f32.f16.f16.f32 "
        "{%0,%1,%2,%3}, {%4,%5,%6,%7}, {%8,%9}, {%0,%1,%2,%3};"
        : "+f"(c[0]), "+f"(c[1]), "+f"(c[2]), "+f"(c[3])
        : "r"(a0), "r"(a1), "r"(a2), "r"(a3), "r"(b0), "r"(b1));
}

__device__ __forceinline__ void ldsm_x4(unsigned& r0, unsigned& r1,
                                        unsigned& r2, unsigned& r3, unsigned addr) {
    asm volatile("ldmatrix.sync.aligned.m8n8.x4.shared.b16 {%0,%1,%2,%3}, [%4];"
                 : "=r"(r0), "=r"(r1), "=r"(r2), "=r"(r3) : "r"(addr));
}
__device__ __forceinline__ void ldsm_x4t(unsigned& r0, unsigned& r1,
                                         unsigned& r2, unsigned& r3, unsigned addr) {
    asm volatile("ldmatrix.sync.aligned.m8n8.x4.trans.shared.b16 {%0,%1,%2,%3}, [%4];"
                 : "=r"(r0), "=r"(r1), "=r"(r2), "=r"(r3) : "r"(addr));
}

__device__ __forceinline__ void cp16(void* smem_dst, const void* gsrc) {
    unsigned d = (unsigned)__cvta_generic_to_shared(smem_dst);
    asm volatile("cp.async.cg.shared.global [%0], [%1], 16;" :: "r"(d), "l"(gsrc));
}
__device__ __forceinline__ void cp16z(void* smem_dst, const void* gsrc, bool ok) {
    unsigned d = (unsigned)__cvta_generic_to_shared(smem_dst);
    int sz = ok ? 16 : 0;
    asm volatile("cp.async.cg.shared.global [%0], [%1], 16, %2;" :: "r"(d), "l"(gsrc), "r"(sz));
}
__device__ __forceinline__ void cp_commit() { asm volatile("cp.async.commit_group;"); }
template <int N>
__device__ __forceinline__ void cp_wait() { asm volatile("cp.async.wait_group %0;" :: "n"(N)); }

// ---------------- fp16 GEMM: 128x128x64 tiles, 3-stage cp.async -------------
// 256 thr, 8 warps of 64x32, 2 CTAs/SM. A always fp16 K-major.
// MODE 0: NT — B is [N,K] row-major.
// MODE 1: NN — B is [K,N] row-major (trans ldmatrix). C = A*B.
// MODE 2: NN-conv split-K2 — A is implicit im2col of token-major [L,D] fp16
//         (token = bye*128+row-1+k/768, zero-padded at ends), K=3*768; B as NT.
//         grid.y packs (M tile, K half): bye = by&3, kh = by>>2.
//         Raw fp32 partials -> C + kh*B*L*D (no epilogue).
// MODE 3: symmetric NT split-K2 (A==B): grid.x = 10 upper-triangle tiles,
//         grid.y = K half; partial kh=0 -> C, kh=1 -> (float*)C16.
//         Off-diag tiles mirror-store C^T via smem stage.
// EPI 0: none. EPI 1: relu(x+bias[n]). EPI 3: pool partials (tanh(x+b1)*w2).
// OUT 0: store fp32 C. OUT 1: store fp16 C16. OUT 2: fp32 C + fp16 Caux.
template <int MODE, int EPI, int OUT>
__global__ __launch_bounds__(256, 2) void gemm_h(
    const __half* __restrict__ A, const __half* __restrict__ Bm,
    float* __restrict__ C, __half* __restrict__ C16, __half* __restrict__ Caux,
    const float* __restrict__ bias, const float* __restrict__ w2,
    float* __restrict__ pp,
    int K, int lda, int ldb, int ldc,
    long sA, long sB, long sC)
{
    constexpr int BM = 128, BN = 128, BK = 64, S = 3;
    constexpr int BKP = 72;   // 64+8 halves pad (144B rows; LDSM conflict-free)
    constexpr int BNP = 136;  // 128+8 halves pad (272B rows; trans-LDSM conflict-free)
    constexpr bool BNN = (MODE == 1);   // B stored [K][N]

    extern __shared__ __half sh[];
    __half* Asm = sh;                         // [S][BM][BKP]
    __half* Bsm = sh + (long)S * BM * BKP;    // NT: [S][BN][BKP]; NN: [S][BK][BNP]

    const int tid = threadIdx.x;
    const int bz = blockIdx.z;
    int bxe = blockIdx.x, bye = blockIdx.y;
    int kh = 0;
    if (MODE == 3) {
        int t = blockIdx.x;
        int r = 0;
        while ((r + 1) * (r + 2) / 2 <= t) r++;
        bye = t - r * (r + 1) / 2;   // 0..r
        bxe = r;
        kh = blockIdx.y;             // K half
    } else if (MODE == 2) {
        bye = blockIdx.y & 3;        // M tile
        kh  = blockIdx.y >> 2;       // K half
    }

    const __half* Ab = A + (long)bz * sA + (MODE == 2 ? 0L : (long)bye * BM * lda);
    const __half* Bb = Bm + (long)bz * sB +
                       (BNN ? (long)bxe * BN : (long)bxe * BN * ldb);

    const int wid  = tid >> 5;
    const int lane = tid & 31;
    const int wm = (wid & 1) * 64;    // 2 warps in M
    const int wn = (wid >> 1) * 32;   // 4 warps in N
    const int gid = lane >> 2;        // 0..7
    const int tig = lane & 3;         // 0..3
    const int lm  = lane & 7;         // ldmatrix row lane
    const int lg  = lane >> 3;        // ldmatrix group 0..3

    float acc[4][4][4];
#pragma unroll
    for (int mt = 0; mt < 4; mt++)
#pragma unroll
        for (int nt = 0; nt < 4; nt++)
#pragma unroll
            for (int r = 0; r < 4; r++) acc[mt][nt][r] = 0.f;

    const int KT    = (MODE == 3 || MODE == 2) ? K / (2 * BK) : K / BK;
    const int kbase = (MODE == 3 || MODE == 2) ? kh * (K / 2) : 0;

    auto issue_copy = [&](int kt, int s) {
        const int k0 = kbase + kt * BK;
        __half* As = Asm + (long)s * BM * BKP;
#pragma unroll
        for (int t = 0; t < 4; t++) {
            int id  = tid + t * 256;
            int row = id >> 3;          // 0..127
            int c8  = (id & 7) * 8;     // 0..56
            if (MODE == 2) {
                int k   = k0 + c8;
                int sub = (k >= 1536) ? 2 : (k >= 768 ? 1 : 0);
                int tok = bye * BM + row - 1 + sub;
                int d   = k - sub * 768;
                bool ok = ((unsigned)tok < (unsigned)LL);
                int tc  = ok ? tok : 0;
                cp16z(As + (long)row * BKP + c8, Ab + (long)tc * DD + d, ok);
            } else {
                cp16(As + (long)row * BKP + c8, Ab + (long)row * lda + k0 + c8);
            }
        }
        if (BNN) {
            __half* Bs = Bsm + (long)s * BK * BNP;
#pragma unroll
            for (int t = 0; t < 4; t++) {
                int id  = tid + t * 256;
                int r   = id >> 4;          // k row 0..63
                int c8  = (id & 15) * 8;    // n col 0..120
                cp16(Bs + (long)r * BNP + c8, Bb + (long)(k0 + r) * ldb + c8);
            }
        } else {
            __half* Bs = Bsm + (long)s * BN * BKP;
#pragma unroll
            for (int t = 0; t < 4; t++) {
                int id  = tid + t * 256;
                int row = id >> 3;
                int c8  = (id & 7) * 8;
                cp16(Bs + (long)row * BKP + c8, Bb + (long)row * ldb + k0 + c8);
            }
        }
        cp_commit();
    };

#pragma unroll
    for (int s = 0; s < S - 1; s++) issue_copy(s, s);

    for (int kt = 0; kt < KT; kt++) {
        const int s = kt % S;
        cp_wait<S - 2>();
        __syncthreads();

        const int pre = kt + S - 1;
        if (pre < KT) issue_copy(pre, pre % S);

        const unsigned uAs = (unsigned)__cvta_generic_to_shared(Asm + (long)s * BM * BKP);
        const unsigned uBs = BNN
            ? (unsigned)__cvta_generic_to_shared(Bsm + (long)s * BK * BNP)
            : (unsigned)__cvta_generic_to_shared(Bsm + (long)s * BN * BKP);

#pragma unroll
        for (int ks = 0; ks < BK; ks += 16) {
            unsigned bf[4][2];
            // paired x4: two nt tiles per ldmatrix (r_i <- address group i)
#pragma unroll
            for (int nt2 = 0; nt2 < 2; nt2++) {
                if (BNN) {
                    int krow = ks + (lg & 1) * 8 + lm;
                    int ncol = wn + nt2 * 16 + (lg >> 1) * 8;
                    ldsm_x4t(bf[2 * nt2][0], bf[2 * nt2][1],
                             bf[2 * nt2 + 1][0], bf[2 * nt2 + 1][1],
                             uBs + (krow * BNP + ncol) * 2);
                } else {
                    int row = wn + nt2 * 16 + (lg >> 1) * 8 + lm;
                    int kk  = ks + (lg & 1) * 8;
                    ldsm_x4(bf[2 * nt2][0], bf[2 * nt2][1],
                            bf[2 * nt2 + 1][0], bf[2 * nt2 + 1][1],
                            uBs + (row * BKP + kk) * 2);
                }
            }
#pragma unroll
            for (int mt = 0; mt < 4; mt++) {
                int row = wm + mt * 16 + lm + (lg & 1) * 8;
                int kk  = ks + (lg >> 1) * 8;
                unsigned a0, a1, a2, a3;
                ldsm_x4(a0, a1, a2, a3, uAs + (row * BKP + kk) * 2);
#pragma unroll
                for (int nt = 0; nt < 4; nt++)
                    mma_f16(acc[mt][nt], a0, a1, a2, a3, bf[nt][0], bf[nt][1]);
            }
        }
    }

    if (EPI == 3) {
        float part[4][2];
#pragma unroll
        for (int mt = 0; mt < 4; mt++) { part[mt][0] = 0.f; part[mt][1] = 0.f; }
#pragma unroll
        for (int nt = 0; nt < 4; nt++) {
            const int c = bxe * BN + wn + nt * 8 + 2 * tig;
            float b0 = bias[c], b1 = bias[c + 1];
            float w0 = w2[c],   w1 = w2[c + 1];
#pragma unroll
            for (int mt = 0; mt < 4; mt++) {
                part[mt][0] += tanhf(acc[mt][nt][0] + b0) * w0
                             + tanhf(acc[mt][nt][1] + b1) * w1;
                part[mt][1] += tanhf(acc[mt][nt][2] + b0) * w0
                             + tanhf(acc[mt][nt][3] + b1) * w1;
            }
        }
#pragma unroll
        for (int o = 1; o <= 2; o <<= 1)
#pragma unroll
            for (int mt = 0; mt < 4; mt++) {
                part[mt][0] += __shfl_xor_sync(0xffffffffu, part[mt][0], o);
                part[mt][1] += __shfl_xor_sync(0xffffffffu, part[mt][1], o);
            }
        if (tig == 0) {
#pragma unroll
            for (int mt = 0; mt < 4; mt++)
#pragma unroll
                for (int half = 0; half < 2; half++) {
                    int row = bye * BM + wm + mt * 16 + gid + half * 8;
                    pp[((long)row * 6 + bxe) * 4 + (wid >> 1)] = part[mt][half];
                }
        }
        return;
    }

    // split-K partial slab selection
    float* Cbase = C;
    if (MODE == 3 && kh == 1) Cbase = reinterpret_cast<float*>(C16);
    if (MODE == 2) Cbase = C + (long)kh * BB * LL * DD;

    const bool mirror = (MODE == 3) && (bxe != bye);
    float* T = reinterpret_cast<float*>(sh);   // 128 x 132 staging (mirror only)
    if (mirror) {
        cp_wait<0>();
        __syncthreads();
    }

    float*  Cf = (OUT != 1) ? (Cbase + (long)bz * sC + (long)(bye * BM) * ldc + bxe * BN) : nullptr;
    __half* Ch = (OUT == 1) ? (C16 + (long)bz * sC + (long)(bye * BM) * ldc + bxe * BN)
               : (OUT == 2) ? (Caux + (long)bz * sC + (long)(bye * BM) * ldc + bxe * BN) : nullptr;
#pragma unroll
    for (int nt = 0; nt < 4; nt++) {
        const int c = wn + nt * 8 + 2 * tig;
        float b0 = 0.f, b1 = 0.f;
        if (EPI == 1) {
            b0 = bias[bxe * BN + c];
            b1 = bias[bxe * BN + c + 1];
        }
#pragma unroll
        for (int mt = 0; mt < 4; mt++) {
            const int r0 = wm + mt * 16 + gid;
            float v0 = acc[mt][nt][0], v1 = acc[mt][nt][1];
            float v2 = acc[mt][nt][2], v3 = acc[mt][nt][3];
            if (EPI == 1) {
                v0 = fmaxf(v0 + b0, 0.f); v1 = fmaxf(v1 + b1, 0.f);
                v2 = fmaxf(v2 + b0, 0.f); v3 = fmaxf(v3 + b1, 0.f);
            }
            if (OUT != 1) {
                *reinterpret_cast<float2*>(Cf + (long)r0 * ldc + c)       = make_float2(v0, v1);
                *reinterpret_cast<float2*>(Cf + (long)(r0 + 8) * ldc + c) = make_float2(v2, v3);
                if (mirror) {
                    T[(c) * 132 + r0]         = v0;
                    T[(c + 1) * 132 + r0]     = v1;
                    T[(c) * 132 + r0 + 8]     = v2;
                    T[(c + 1) * 132 + r0 + 8] = v3;
                }
            }
            if (OUT != 0) {
                *reinterpret_cast<__half2*>(Ch + (long)r0 * ldc + c)       = __floats2half2_rn(v0, v1);
                *reinterpret_cast<__half2*>(Ch + (long)(r0 + 8) * ldc + c) = __floats2half2_rn(v2, v3);
            }
        }
    }

    if (mirror) {
        __syncthreads();
        float* Cm = Cbase + (long)bz * sC + (long)(bxe * BN) * ldc + bye * BM;
#pragma unroll
        for (int t = 0; t < 16; t++) {
            int id = t * 256 + tid;
            int r2 = id >> 5;
            int c4 = (id & 31) * 4;
            float4 v = *reinterpret_cast<const float4*>(&T[r2 * 132 + c4]);
            *reinterpret_cast<float4*>(Cm + (long)r2 * ldc + c4) = v;
        }
    }
}

// ---------------- inputs fp32 -> fp16 ----------------------------------------
__global__ void round_half(const float* __restrict__ src, __half* __restrict__ dst, int n)
{
    for (int i = blockIdx.x * blockDim.x + threadIdx.x; i * 4 < n;
         i += gridDim.x * blockDim.x) {
        float4 v = *reinterpret_cast<const float4*>(src + i * 4);
        *reinterpret_cast<__half2*>(dst + i * 4)     = __floats2half2_rn(v.x, v.y);
        *reinterpret_cast<__half2*>(dst + i * 4 + 2) = __floats2half2_rn(v.z, v.w);
    }
}

// ------- conv combine: sum 2 split-K partials + bias + relu -> fp16 (+fp32) --
__global__ void conv_combine(const float* __restrict__ P, const float* __restrict__ bias,
                             __half* __restrict__ dst16, float* __restrict__ dst32)
{
    const long SLAB = (long)BB * LL * DD;
    const int n4 = BB * LL * DD / 4;
    for (int i = blockIdx.x * blockDim.x + threadIdx.x; i < n4;
         i += gridDim.x * blockDim.x) {
        long e = (long)i * 4;
        int d = (int)(e % DD);
        float4 a = *reinterpret_cast<const float4*>(P + e);
        float4 b = *reinterpret_cast<const float4*>(P + e + SLAB);
        float v0 = fmaxf(a.x + b.x + bias[d],     0.f);
        float v1 = fmaxf(a.y + b.y + bias[d + 1], 0.f);
        float v2 = fmaxf(a.z + b.z + bias[d + 2], 0.f);
        float v3 = fmaxf(a.w + b.w + bias[d + 3], 0.f);
        *reinterpret_cast<__half2*>(dst16 + e)     = __floats2half2_rn(v0, v1);
        *reinterpret_cast<__half2*>(dst16 + e + 2) = __floats2half2_rn(v2, v3);
        if (dst32) *reinterpret_cast<float4*>(dst32 + e) = make_float4(v0, v1, v2, v3);
    }
}

// ------- invn from Gram diagonal: invn[l] = 1/max(sqrt(S+S2),1e-12) ----------
__global__ void diag_kernel(const float* __restrict__ S, const float* __restrict__ S2,
                            float* __restrict__ invn)
{
    int i = blockIdx.x * blockDim.x + threadIdx.x;
    if (i >= BB * LL) return;
    int b = i / LL, l = i - b * LL;
    long off = (long)b * LL * LL + (long)l * LL + l;
    float ss = S[off] + S2[off];
    invn[i] = 1.f / fmaxf(sqrtf(fmaxf(ss, 0.f)), 1e-12f);
}

// ------- masked softmax: sums split-K partials, optional cosine scale --------
__global__ void softmask_kernel(const float* __restrict__ S, const float* __restrict__ S2,
                                __half* __restrict__ SH,
                                const float* __restrict__ mask,
                                const float* __restrict__ invn)
{
    int gw   = (blockIdx.x * blockDim.x + threadIdx.x) >> 5;
    int lane = threadIdx.x & 31;
    if (gw >= BB * LL) return;
    int b = gw / LL;
    int l = gw - b * LL;
    const float* row  = S  + (long)gw * LL;
    const float* row2 = S2 + (long)gw * LL;
    __half* rowH = SH + (long)gw * LL;
    const float* mk = mask + (long)b * LL;

    float il = invn ? invn[gw] : 1.f;
    float v[16];
    float mx = -1e30f;
#pragma unroll
    for (int t = 0; t < 16; t++) {
        int m = lane + t * 32;
        float s = row[m] + row2[m];
        if (invn) s *= il * invn[b * LL + m];
        v[t] = s;
        mx = fmaxf(mx, s);
    }
#pragma unroll
    for (int o = 16; o; o >>= 1) mx = fmaxf(mx, __shfl_xor_sync(0xffffffffu, mx, o));

    float sum = 0.f;
#pragma unroll
    for (int t = 0; t < 16; t++) {
        float e = __expf(v[t] - mx) * mk[lane + t * 32];
        v[t] = e;
        sum += e;
    }
#pragma unroll
    for (int o = 16; o; o >>= 1) sum += __shfl_xor_sync(0xffffffffu, sum, o);

    float scale = mk[l] / (sum + 1e-10f);
#pragma unroll
    for (int t = 0; t < 16; t++) rowH[lane + t * 32] = __float2half_rn(v[t] * scale);
}

// ------- conv weight: W[h][o][i][tap] -> wtH[h][o][tap*768+i] fp16 -----------
__global__ void wtrans_kernel(const float* __restrict__ W)
{
    const long n = (long)HOPS * DD * 3 * DD;
    for (long i = blockIdx.x * (long)blockDim.x + threadIdx.x; i < n;
         i += (long)gridDim.x * blockDim.x) {
        long h   = i / ((long)DD * 3 * DD);
        long rem = i - h * (long)DD * 3 * DD;
        long o   = rem / (3 * DD);
        long k   = rem - o * 3 * DD;
        long tap = k / DD;
        long ii  = k - tap * DD;
        g_wtH[i] = __float2half_rn(W[((h * DD + o) * DD + ii) * 3 + tap]);
    }
}

// ------- pool W1 -> transposed fp16 [e][d], coalesced tile transpose ---------
__global__ void w1trans_kernel(const float* __restrict__ W1)
{
    __shared__ float t[32][33];
    int d0 = blockIdx.x * 32, e0 = blockIdx.y * 32;
    int x = threadIdx.x, y0 = threadIdx.y;   // 32 x 8
#pragma unroll
    for (int i = 0; i < 4; i++) {
        int y = y0 + i * 8;
        t[y][x] = W1[(d0 + y) * DD + e0 + x];
    }
    __syncthreads();
#pragma unroll
    for (int i = 0; i < 4; i++) {
        int y = y0 + i * 8;
        g_w1T[(long)(e0 + y) * DD + d0 + x] = __float2half_rn(t[x][y]);
    }
}

// ---------------- pooling tail ----------------------------------------------
__global__ void pool_finalize_kernel(const float* __restrict__ b2,
                                     float* __restrict__ out)
{
    int gw   = (blockIdx.x * blockDim.x + threadIdx.x) >> 5;
    int lane = threadIdx.x & 31;
    if (gw >= BB * LL) return;
    const __half* res = g_resultrH + (long)gw * NH * DD;

    float s[NH];
#pragma unroll
    for (int h = 0; h < NH; h++) {
        float p = (lane < 24) ? g_pp[(long)(gw * NH + h) * 24 + lane] : 0.f;
#pragma unroll
        for (int o = 16; o; o >>= 1) p += __shfl_xor_sync(0xffffffffu, p, o);
        s[h] = p + b2[0];
    }
    float mx = fmaxf(fmaxf(s[0], s[1]), fmaxf(s[2], s[3]));
    float e0 = __expf(s[0] - mx), e1 = __expf(s[1] - mx);
    float e2 = __expf(s[2] - mx), e3 = __expf(s[3] - mx);
    float inv = 1.f / (e0 + e1 + e2 + e3);
    e0 *= inv; e1 *= inv; e2 *= inv; e3 *= inv;

    float* o = out + (long)gw * DD;
#pragma unroll
    for (int t = 0; t < 24; t++) {
        int d = lane + t * 32;
        o[d] = e0 * __half2float(res[d]) + e1 * __half2float(res[DD + d])
             + e2 * __half2float(res[2 * DD + d]) + e3 * __half2float(res[3 * DD + d]);
    }
}

// ---------------- orchestration ---------------------------------------------
extern "C" void kernel_launch(void* const* d_in, const int* in_sizes, int n_in,
                              void* d_out, int out_size)
{
    (void)in_sizes; (void)n_in; (void)out_size;
    const float* inputs  = (const float*)d_in[0];
    const float* mask    = (const float*)d_in[1];
    const float* conv_w  = (const float*)d_in[2];
    const float* conv_b  = (const float*)d_in[3];
    const float* pool_w1 = (const float*)d_in[4];
    const float* pool_b1 = (const float*)d_in[5];
    const float* pool_w2 = (const float*)d_in[6];
    const float* pool_b2 = (const float*)d_in[7];
    float* out = (float*)d_out;

    __half *inrH, *convrH0, *convrH1, *scoresH, *resultrH, *wtH, *w1T;
    float *scores, *scores2, *convP, *pp, *invn;
    cudaGetSymbolAddress((void**)&inrH,     g_inrH);
    cudaGetSymbolAddress((void**)&convrH0,  g_convrH0);
    cudaGetSymbolAddress((void**)&convrH1,  g_convrH1);
    cudaGetSymbolAddress((void**)&scores,   g_scores);
    cudaGetSymbolAddress((void**)&scores2,  g_scores2);
    cudaGetSymbolAddress((void**)&convP,    g_convP);
    cudaGetSymbolAddress((void**)&scoresH,  g_scoresH);
    cudaGetSymbolAddress((void**)&resultrH, g_resultrH);
    cudaGetSymbolAddress((void**)&wtH,      g_wtH);
    cudaGetSymbolAddress((void**)&w1T,      g_w1T);
    cudaGetSymbolAddress((void**)&pp,       g_pp);
    cudaGetSymbolAddress((void**)&invn,     g_invn);

    constexpr int SMEM = 3 * (128 * 72 + 128 * 72) * 2;  // 110592 B (max of modes)
    cudaFuncSetAttribute(gemm_h<3, 0, 0>, cudaFuncAttributeMaxDynamicSharedMemorySize, SMEM);
    cudaFuncSetAttribute(gemm_h<1, 0, 1>, cudaFuncAttributeMaxDynamicSharedMemorySize, SMEM);
    cudaFuncSetAttribute(gemm_h<2, 0, 0>, cudaFuncAttributeMaxDynamicSharedMemorySize, SMEM);
    cudaFuncSetAttribute(gemm_h<0, 3, 0>, cudaFuncAttributeMaxDynamicSharedMemorySize, SMEM);

    // setup: fp16 operands
    round_half<<<1024, 256>>>(inputs, inrH, BB * LL * DD);
    wtrans_kernel<<<512, 256>>>(conv_w);
    w1trans_kernel<<<dim3(DD / 32, DD / 32), dim3(32, 8)>>>(pool_w1);

    // ---- hop 0: raw similarity on inputs (symmetric split-K2) ----
    gemm_h<3, 0, 0><<<dim3(10, 2, BB), 256, SMEM>>>(
        inrH, inrH, scores, (__half*)scores2, nullptr, nullptr, nullptr, nullptr,
        DD, DD, DD, LL, (long)LL * DD, (long)LL * DD, (long)LL * LL);
    softmask_kernel<<<BB * LL / 8, 256>>>(scores, scores2, scoresH, mask, nullptr);
    gemm_h<1, 0, 1><<<dim3(DD / 128, LL / 128, BB), 256, SMEM>>>(
        scoresH, inrH, nullptr, resultrH, nullptr, nullptr, nullptr, nullptr,
        LL, LL, DD, NH * DD, (long)LL * LL, (long)LL * DD, (long)LL * NH * DD);

    // ---- hops 1..3 ----
    const __half* curH = inrH;   // token-major fp16 current sequence
    for (int h = 0; h < HOPS; h++) {
        __half* crDst = (h & 1) ? convrH1 : convrH0;
        // conv as split-K2 raw-partial GEMM (768 CTAs ~ 1.5 wave makespan)
        gemm_h<2, 0, 0><<<dim3(DD / 128, 8, BB), 256, SMEM>>>(
            curH, wtH + (long)h * DD * 3 * DD, convP, nullptr, nullptr,
            nullptr, nullptr, nullptr,
            3 * DD, 0, 3 * DD, DD, (long)LL * DD, 0L, (long)LL * DD);
        // combine partials + bias + relu -> fp16 (+fp32 to d_out on last hop)
        conv_combine<<<2048, 256>>>(convP, conv_b + h * DD, crDst,
                                    (h == HOPS - 1) ? out : nullptr);
        // raw Gram matrix on un-normalized conv (symmetric, split-K2)
        gemm_h<3, 0, 0><<<dim3(10, 2, BB), 256, SMEM>>>(
            crDst, crDst, scores, (__half*)scores2, nullptr, nullptr, nullptr, nullptr,
            DD, DD, DD, LL, (long)LL * DD, (long)LL * DD, (long)LL * LL);
        // row norms from the Gram diagonal
        diag_kernel<<<(BB * LL + 255) / 256, 256>>>(scores, scores2, invn);
        softmask_kernel<<<BB * LL / 8, 256>>>(scores, scores2, scoresH, mask, invn);
        gemm_h<1, 0, 1><<<dim3(DD / 128, LL / 128, BB), 256, SMEM>>>(
            scoresH, crDst, nullptr, resultrH + (long)(h + 1) * DD, nullptr,
            nullptr, nullptr, nullptr,
            LL, LL, DD, NH * DD, (long)LL * LL, (long)LL * DD, (long)LL * NH * DD);
        curH = crDst;
    }

    // pooling: fused tanh(result@W1+b1)·w2 partials
    gemm_h<0, 3, 0><<<dim3(DD / 128, (BB * LL * NH) / 128, 1), 256, SMEM>>>(
        resultrH, w1T, nullptr, nullptr, nullptr, pool_b1, pool_w2, pp,
        DD, DD, DD, DD, 0L, 0L, 0L);

    // output #2: weighted
    pool_finalize_kernel<<<BB * LL / 8, 256>>>(pool_b2, out + (long)BB * LL * DD);
}

// round 17
// speedup vs baseline: 1.5908x; 1.5908x over previous
#include <cuda_runtime.h>
#include <cuda_fp16.h>
#include <math.h>

#define BB 16
#define LL 512
#define DD 768
#define HOPS 3
#define NH (HOPS + 1)

// ---------------- scratch (static device globals; no allocs) ----------------
__device__ __align__(16) __half g_inrH[(long)BB * LL * DD];     // inputs fp16, token-major
__device__ __align__(16) __half g_convrH0[(long)BB * LL * DD];  // conv fp16 (ping)
__device__ __align__(16) __half g_convrH1[(long)BB * LL * DD];  // conv fp16 (pong)
__device__ __align__(16) float  g_scores[(long)BB * LL * LL];   // scores partial (K half 0)
__device__ __align__(16) float  g_scores2[(long)BB * LL * LL];  // scores partial (K half 1)
__device__ __align__(16) __half g_scoresH[(long)BB * LL * LL];  // post-softmax fp16
__device__ __align__(16) __half g_resultrH[(long)BB * LL * NH * DD]; // [B,L,4,D] fp16
__device__ __align__(16) __half g_wtH[(long)HOPS * DD * 3 * DD];     // conv W [h][o][k] K-major
__device__ __align__(16) __half g_w1T[(long)DD * DD];                // pool W1^T [e][d]
__device__ __align__(16) float  g_pp[(long)BB * LL * NH * 24];       // pool-score partials
__device__ __align__(16) float  g_invn[(long)BB * LL];               // 1/||conv row||

// ---------------- mma m16n8k16 fp16 -> fp32 ---------------------------------
__device__ __forceinline__ void mma_f16(float c[4],
                                        unsigned a0, unsigned a1, unsigned a2, unsigned a3,
                                        unsigned b0, unsigned b1) {
    asm volatile(
        "mma.sync.aligned.m16n8k16.row.col.f32.f16.f16.f32 "
        "{%0,%1,%2,%3}, {%4,%5,%6,%7}, {%8,%9}, {%0,%1,%2,%3};"
        : "+f"(c[0]), "+f"(c[1]), "+f"(c[2]), "+f"(c[3])
        : "r"(a0), "r"(a1), "r"(a2), "r"(a3), "r"(b0), "r"(b1));
}

__device__ __forceinline__ void ldsm_x4(unsigned& r0, unsigned& r1,
                                        unsigned& r2, unsigned& r3, unsigned addr) {
    asm volatile("ldmatrix.sync.aligned.m8n8.x4.shared.b16 {%0,%1,%2,%3}, [%4];"
                 : "=r"(r0), "=r"(r1), "=r"(r2), "=r"(r3) : "r"(addr));
}
__device__ __forceinline__ void ldsm_x4t(unsigned& r0, unsigned& r1,
                                         unsigned& r2, unsigned& r3, unsigned addr) {
    asm volatile("ldmatrix.sync.aligned.m8n8.x4.trans.shared.b16 {%0,%1,%2,%3}, [%4];"
                 : "=r"(r0), "=r"(r1), "=r"(r2), "=r"(r3) : "r"(addr));
}

__device__ __forceinline__ void cp16(void* smem_dst, const void* gsrc) {
    unsigned d = (unsigned)__cvta_generic_to_shared(smem_dst);
    asm volatile("cp.async.cg.shared.global [%0], [%1], 16;" :: "r"(d), "l"(gsrc));
}
__device__ __forceinline__ void cp16z(void* smem_dst, const void* gsrc, bool ok) {
    unsigned d = (unsigned)__cvta_generic_to_shared(smem_dst);
    int sz = ok ? 16 : 0;
    asm volatile("cp.async.cg.shared.global [%0], [%1], 16, %2;" :: "r"(d), "l"(gsrc), "r"(sz));
}
__device__ __forceinline__ void cp_commit() { asm volatile("cp.async.commit_group;"); }
template <int N>
__device__ __forceinline__ void cp_wait() { asm volatile("cp.async.wait_group %0;" :: "n"(N)); }

// ---------------- fp16 GEMM: 128x128x64 tiles, 3-stage cp.async -------------
// 256 thr, 8 warps of 64x32, 2 CTAs/SM. A always fp16 K-major.
// MODE 0: NT — B is [N,K] row-major.
// MODE 1: NN — B is [K,N] row-major (trans ldmatrix). C = A*B.
// MODE 2: NN-conv A side — A is implicit im2col of token-major [L,D] fp16
//         (token = by*128+row-1+k/768, zero-padded at ends), K=3*768; B as NT.
// MODE 3: symmetric NT split-K2 (A==B): grid.x = 10 upper-triangle tiles,
//         grid.y = K half; partial kh=0 -> C, kh=1 -> (float*)C16.
//         Off-diag tiles mirror-store C^T via smem stage.
// EPI 0: none. EPI 1: relu(x+bias[n]). EPI 3: pool partials (tanh(x+b1)*w2).
// OUT 0: store fp32 C. OUT 1: store fp16 C16. OUT 2: fp32 C + fp16 Caux.
template <int MODE, int EPI, int OUT>
__global__ __launch_bounds__(256, 2) void gemm_h(
    const __half* __restrict__ A, const __half* __restrict__ Bm,
    float* __restrict__ C, __half* __restrict__ C16, __half* __restrict__ Caux,
    const float* __restrict__ bias, const float* __restrict__ w2,
    float* __restrict__ pp,
    int K, int lda, int ldb, int ldc,
    long sA, long sB, long sC)
{
    constexpr int BM = 128, BN = 128, BK = 64, S = 3;
    constexpr int BKP = 72;   // 64+8 halves pad (144B rows; LDSM conflict-free)
    constexpr int BNP = 136;  // 128+8 halves pad (272B rows; trans-LDSM conflict-free)
    constexpr bool BNN = (MODE == 1);   // B stored [K][N]

    extern __shared__ __half sh[];
    __half* Asm = sh;                         // [S][BM][BKP]
    __half* Bsm = sh + (long)S * BM * BKP;    // NT: [S][BN][BKP]; NN: [S][BK][BNP]

    const int tid = threadIdx.x;
    const int bz = blockIdx.z;
    int bxe = blockIdx.x, bye = blockIdx.y;
    int kh = 0;
    if (MODE == 3) {
        int t = blockIdx.x;
        int r = 0;
        while ((r + 1) * (r + 2) / 2 <= t) r++;
        bye = t - r * (r + 1) / 2;   // 0..r
        bxe = r;
        kh = blockIdx.y;             // K half
    }

    const __half* Ab = A + (long)bz * sA + (MODE == 2 ? 0L : (long)bye * BM * lda);
    const __half* Bb = Bm + (long)bz * sB +
                       (BNN ? (long)bxe * BN : (long)bxe * BN * ldb);

    const int wid  = tid >> 5;
    const int lane = tid & 31;
    const int wm = (wid & 1) * 64;    // 2 warps in M
    const int wn = (wid >> 1) * 32;   // 4 warps in N
    const int gid = lane >> 2;        // 0..7
    const int tig = lane & 3;         // 0..3
    const int lm  = lane & 7;         // ldmatrix row lane
    const int lg  = lane >> 3;        // ldmatrix group 0..3

    float acc[4][4][4];
#pragma unroll
    for (int mt = 0; mt < 4; mt++)
#pragma unroll
        for (int nt = 0; nt < 4; nt++)
#pragma unroll
            for (int r = 0; r < 4; r++) acc[mt][nt][r] = 0.f;

    const int KT    = (MODE == 3) ? K / (2 * BK) : K / BK;
    const int kbase = (MODE == 3) ? kh * (K / 2) : 0;

    auto issue_copy = [&](int kt, int s) {
        const int k0 = kbase + kt * BK;
        __half* As = Asm + (long)s * BM * BKP;
#pragma unroll
        for (int t = 0; t < 4; t++) {
            int id  = tid + t * 256;
            int row = id >> 3;          // 0..127
            int c8  = (id & 7) * 8;     // 0..56
            if (MODE == 2) {
                int k   = k0 + c8;
                int sub = (k >= 1536) ? 2 : (k >= 768 ? 1 : 0);
                int tok = bye * BM + row - 1 + sub;
                int d   = k - sub * 768;
                bool ok = ((unsigned)tok < (unsigned)LL);
                int tc  = ok ? tok : 0;
                cp16z(As + (long)row * BKP + c8, Ab + (long)tc * DD + d, ok);
            } else {
                cp16(As + (long)row * BKP + c8, Ab + (long)row * lda + k0 + c8);
            }
        }
        if (BNN) {
            __half* Bs = Bsm + (long)s * BK * BNP;
#pragma unroll
            for (int t = 0; t < 4; t++) {
                int id  = tid + t * 256;
                int r   = id >> 4;          // k row 0..63
                int c8  = (id & 15) * 8;    // n col 0..120
                cp16(Bs + (long)r * BNP + c8, Bb + (long)(k0 + r) * ldb + c8);
            }
        } else {
            __half* Bs = Bsm + (long)s * BN * BKP;
#pragma unroll
            for (int t = 0; t < 4; t++) {
                int id  = tid + t * 256;
                int row = id >> 3;
                int c8  = (id & 7) * 8;
                cp16(Bs + (long)row * BKP + c8, Bb + (long)row * ldb + k0 + c8);
            }
        }
        cp_commit();
    };

#pragma unroll
    for (int s = 0; s < S - 1; s++) issue_copy(s, s);

    for (int kt = 0; kt < KT; kt++) {
        const int s = kt % S;
        cp_wait<S - 2>();
        __syncthreads();

        const int pre = kt + S - 1;
        if (pre < KT) issue_copy(pre, pre % S);

        const unsigned uAs = (unsigned)__cvta_generic_to_shared(Asm + (long)s * BM * BKP);
        const unsigned uBs = BNN
            ? (unsigned)__cvta_generic_to_shared(Bsm + (long)s * BK * BNP)
            : (unsigned)__cvta_generic_to_shared(Bsm + (long)s * BN * BKP);

#pragma unroll
        for (int ks = 0; ks < BK; ks += 16) {
            unsigned bf[4][2];
            // paired x4: two nt tiles per ldmatrix (r_i <- address group i)
#pragma unroll
            for (int nt2 = 0; nt2 < 2; nt2++) {
                if (BNN) {
                    int krow = ks + (lg & 1) * 8 + lm;
                    int ncol = wn + nt2 * 16 + (lg >> 1) * 8;
                    ldsm_x4t(bf[2 * nt2][0], bf[2 * nt2][1],
                             bf[2 * nt2 + 1][0], bf[2 * nt2 + 1][1],
                             uBs + (krow * BNP + ncol) * 2);
                } else {
                    int row = wn + nt2 * 16 + (lg >> 1) * 8 + lm;
                    int kk  = ks + (lg & 1) * 8;
                    ldsm_x4(bf[2 * nt2][0], bf[2 * nt2][1],
                            bf[2 * nt2 + 1][0], bf[2 * nt2 + 1][1],
                            uBs + (row * BKP + kk) * 2);
                }
            }
#pragma unroll
            for (int mt = 0; mt < 4; mt++) {
                int row = wm + mt * 16 + lm + (lg & 1) * 8;
                int kk  = ks + (lg >> 1) * 8;
                unsigned a0, a1, a2, a3;
                ldsm_x4(a0, a1, a2, a3, uAs + (row * BKP + kk) * 2);
#pragma unroll
                for (int nt = 0; nt < 4; nt++)
                    mma_f16(acc[mt][nt], a0, a1, a2, a3, bf[nt][0], bf[nt][1]);
            }
        }
    }

    if (EPI == 3) {
        float part[4][2];
#pragma unroll
        for (int mt = 0; mt < 4; mt++) { part[mt][0] = 0.f; part[mt][1] = 0.f; }
#pragma unroll
        for (int nt = 0; nt < 4; nt++) {
            const int c = bxe * BN + wn + nt * 8 + 2 * tig;
            float b0 = bias[c], b1 = bias[c + 1];
            float w0 = w2[c],   w1 = w2[c + 1];
#pragma unroll
            for (int mt = 0; mt < 4; mt++) {
                part[mt][0] += tanhf(acc[mt][nt][0] + b0) * w0
                             + tanhf(acc[mt][nt][1] + b1) * w1;
                part[mt][1] += tanhf(acc[mt][nt][2] + b0) * w0
                             + tanhf(acc[mt][nt][3] + b1) * w1;
            }
        }
#pragma unroll
        for (int o = 1; o <= 2; o <<= 1)
#pragma unroll
            for (int mt = 0; mt < 4; mt++) {
                part[mt][0] += __shfl_xor_sync(0xffffffffu, part[mt][0], o);
                part[mt][1] += __shfl_xor_sync(0xffffffffu, part[mt][1], o);
            }
        if (tig == 0) {
#pragma unroll
            for (int mt = 0; mt < 4; mt++)
#pragma unroll
                for (int half = 0; half < 2; half++) {
                    int row = bye * BM + wm + mt * 16 + gid + half * 8;
                    pp[((long)row * 6 + bxe) * 4 + (wid >> 1)] = part[mt][half];
                }
        }
        return;
    }

    // MODE 3: select partial buffer by K half
    float* Cbase = (MODE == 3 && kh == 1) ? reinterpret_cast<float*>(C16) : C;

    const bool mirror = (MODE == 3) && (bxe != bye);
    float* T = reinterpret_cast<float*>(sh);   // 128 x 132 staging (mirror only)
    if (mirror) {
        cp_wait<0>();
        __syncthreads();
    }

    float*  Cf = (OUT != 1) ? (Cbase + (long)bz * sC + (long)(bye * BM) * ldc + bxe * BN) : nullptr;
    __half* Ch = (OUT == 1) ? (C16 + (long)bz * sC + (long)(bye * BM) * ldc + bxe * BN)
               : (OUT == 2) ? (Caux + (long)bz * sC + (long)(bye * BM) * ldc + bxe * BN) : nullptr;
#pragma unroll
    for (int nt = 0; nt < 4; nt++) {
        const int c = wn + nt * 8 + 2 * tig;
        float b0 = 0.f, b1 = 0.f;
        if (EPI == 1) {
            b0 = bias[bxe * BN + c];
            b1 = bias[bxe * BN + c + 1];
        }
#pragma unroll
        for (int mt = 0; mt < 4; mt++) {
            const int r0 = wm + mt * 16 + gid;
            float v0 = acc[mt][nt][0], v1 = acc[mt][nt][1];
            float v2 = acc[mt][nt][2], v3 = acc[mt][nt][3];
            if (EPI == 1) {
                v0 = fmaxf(v0 + b0, 0.f); v1 = fmaxf(v1 + b1, 0.f);
                v2 = fmaxf(v2 + b0, 0.f); v3 = fmaxf(v3 + b1, 0.f);
            }
            if (OUT != 1) {
                *reinterpret_cast<float2*>(Cf + (long)r0 * ldc + c)       = make_float2(v0, v1);
                *reinterpret_cast<float2*>(Cf + (long)(r0 + 8) * ldc + c) = make_float2(v2, v3);
                if (mirror) {
                    T[(c) * 132 + r0]         = v0;
                    T[(c + 1) * 132 + r0]     = v1;
                    T[(c) * 132 + r0 + 8]     = v2;
                    T[(c + 1) * 132 + r0 + 8] = v3;
                }
            }
            if (OUT != 0) {
                *reinterpret_cast<__half2*>(Ch + (long)r0 * ldc + c)       = __floats2half2_rn(v0, v1);
                *reinterpret_cast<__half2*>(Ch + (long)(r0 + 8) * ldc + c) = __floats2half2_rn(v2, v3);
            }
        }
    }

    if (mirror) {
        __syncthreads();
        float* Cm = Cbase + (long)bz * sC + (long)(bxe * BN) * ldc + bye * BM;
#pragma unroll
        for (int t = 0; t < 16; t++) {
            int id = t * 256 + tid;
            int r2 = id >> 5;
            int c4 = (id & 31) * 4;
            float4 v = *reinterpret_cast<const float4*>(&T[r2 * 132 + c4]);
            *reinterpret_cast<float4*>(Cm + (long)r2 * ldc + c4) = v;
        }
    }
}

// ---------------- inputs fp32 -> fp16 ----------------------------------------
__global__ void round_half(const float* __restrict__ src, __half* __restrict__ dst, int n)
{
    for (int i = blockIdx.x * blockDim.x + threadIdx.x; i * 4 < n;
         i += gridDim.x * blockDim.x) {
        float4 v = *reinterpret_cast<const float4*>(src + i * 4);
        *reinterpret_cast<__half2*>(dst + i * 4)     = __floats2half2_rn(v.x, v.y);
        *reinterpret_cast<__half2*>(dst + i * 4 + 2) = __floats2half2_rn(v.z, v.w);
    }
}

// ------- invn from Gram diagonal: invn[l] = 1/max(sqrt(S+S2),1e-12) ----------
__global__ void diag_kernel(const float* __restrict__ S, const float* __restrict__ S2,
                            float* __restrict__ invn)
{
    int i = blockIdx.x * blockDim.x + threadIdx.x;
    if (i >= BB * LL) return;
    int b = i / LL, l = i - b * LL;
    long off = (long)b * LL * LL + (long)l * LL + l;
    float ss = S[off] + S2[off];
    invn[i] = 1.f / fmaxf(sqrtf(fmaxf(ss, 0.f)), 1e-12f);
}

// ------- masked softmax: sums split-K partials, optional cosine scale --------
__global__ void softmask_kernel(const float* __restrict__ S, const float* __restrict__ S2,
                                __half* __restrict__ SH,
                                const float* __restrict__ mask,
                                const float* __restrict__ invn)
{
    int gw   = (blockIdx.x * blockDim.x + threadIdx.x) >> 5;
    int lane = threadIdx.x & 31;
    if (gw >= BB * LL) return;
    int b = gw / LL;
    int l = gw - b * LL;
    const float* row  = S  + (long)gw * LL;
    const float* row2 = S2 + (long)gw * LL;
    __half* rowH = SH + (long)gw * LL;
    const float* mk = mask + (long)b * LL;

    float il = invn ? invn[gw] : 1.f;
    float v[16];
    float mx = -1e30f;
#pragma unroll
    for (int t = 0; t < 16; t++) {
        int m = lane + t * 32;
        float s = row[m] + row2[m];
        if (invn) s *= il * invn[b * LL + m];
        v[t] = s;
        mx = fmaxf(mx, s);
    }
#pragma unroll
    for (int o = 16; o; o >>= 1) mx = fmaxf(mx, __shfl_xor_sync(0xffffffffu, mx, o));

    float sum = 0.f;
#pragma unroll
    for (int t = 0; t < 16; t++) {
        float e = __expf(v[t] - mx) * mk[lane + t * 32];
        v[t] = e;
        sum += e;
    }
#pragma unroll
    for (int o = 16; o; o >>= 1) sum += __shfl_xor_sync(0xffffffffu, sum, o);

    float scale = mk[l] / (sum + 1e-10f);
#pragma unroll
    for (int t = 0; t < 16; t++) rowH[lane + t * 32] = __float2half_rn(v[t] * scale);
}

// ------- conv weight: W[h][o][i][tap] -> wtH[h][o][tap*768+i] fp16 -----------
__global__ void wtrans_kernel(const float* __restrict__ W)
{
    const long n = (long)HOPS * DD * 3 * DD;
    for (long i = blockIdx.x * (long)blockDim.x + threadIdx.x; i < n;
         i += (long)gridDim.x * blockDim.x) {
        long h   = i / ((long)DD * 3 * DD);
        long rem = i - h * (long)DD * 3 * DD;
        long o   = rem / (3 * DD);
        long k   = rem - o * 3 * DD;
        long tap = k / DD;
        long ii  = k - tap * DD;
        g_wtH[i] = __float2half_rn(W[((h * DD + o) * DD + ii) * 3 + tap]);
    }
}

// ------- pool W1 -> transposed fp16 [e][d], coalesced tile transpose ---------
__global__ void w1trans_kernel(const float* __restrict__ W1)
{
    __shared__ float t[32][33];
    int d0 = blockIdx.x * 32, e0 = blockIdx.y * 32;
    int x = threadIdx.x, y0 = threadIdx.y;   // 32 x 8
#pragma unroll
    for (int i = 0; i < 4; i++) {
        int y = y0 + i * 8;
        t[y][x] = W1[(d0 + y) * DD + e0 + x];
    }
    __syncthreads();
#pragma unroll
    for (int i = 0; i < 4; i++) {
        int y = y0 + i * 8;
        g_w1T[(long)(e0 + y) * DD + d0 + x] = __float2half_rn(t[x][y]);
    }
}

// ---------------- pooling tail ----------------------------------------------
__global__ void pool_finalize_kernel(const float* __restrict__ b2,
                                     float* __restrict__ out)
{
    int gw   = (blockIdx.x * blockDim.x + threadIdx.x) >> 5;
    int lane = threadIdx.x & 31;
    if (gw >= BB * LL) return;
    const __half* res = g_resultrH + (long)gw * NH * DD;

    float s[NH];
#pragma unroll
    for (int h = 0; h < NH; h++) {
        float p = (lane < 24) ? g_pp[(long)(gw * NH + h) * 24 + lane] : 0.f;
#pragma unroll
        for (int o = 16; o; o >>= 1) p += __shfl_xor_sync(0xffffffffu, p, o);
        s[h] = p + b2[0];
    }
    float mx = fmaxf(fmaxf(s[0], s[1]), fmaxf(s[2], s[3]));
    float e0 = __expf(s[0] - mx), e1 = __expf(s[1] - mx);
    float e2 = __expf(s[2] - mx), e3 = __expf(s[3] - mx);
    float inv = 1.f / (e0 + e1 + e2 + e3);
    e0 *= inv; e1 *= inv; e2 *= inv; e3 *= inv;

    float* o = out + (long)gw * DD;
#pragma unroll
    for (int t = 0; t < 24; t++) {
        int d = lane + t * 32;
        o[d] = e0 * __half2float(res[d]) + e1 * __half2float(res[DD + d])
             + e2 * __half2float(res[2 * DD + d]) + e3 * __half2float(res[3 * DD + d]);
    }
}

// ---------------- orchestration ---------------------------------------------
extern "C" void kernel_launch(void* const* d_in, const int* in_sizes, int n_in,
                              void* d_out, int out_size)
{
    (void)in_sizes; (void)n_in; (void)out_size;
    const float* inputs  = (const float*)d_in[0];
    const float* mask    = (const float*)d_in[1];
    const float* conv_w  = (const float*)d_in[2];
    const float* conv_b  = (const float*)d_in[3];
    const float* pool_w1 = (const float*)d_in[4];
    const float* pool_b1 = (const float*)d_in[5];
    const float* pool_w2 = (const float*)d_in[6];
    const float* pool_b2 = (const float*)d_in[7];
    float* out = (float*)d_out;

    __half *inrH, *convrH0, *convrH1, *scoresH, *resultrH, *wtH, *w1T;
    float *scores, *scores2, *pp, *invn;
    cudaGetSymbolAddress((void**)&inrH,     g_inrH);
    cudaGetSymbolAddress((void**)&convrH0,  g_convrH0);
    cudaGetSymbolAddress((void**)&convrH1,  g_convrH1);
    cudaGetSymbolAddress((void**)&scores,   g_scores);
    cudaGetSymbolAddress((void**)&scores2,  g_scores2);
    cudaGetSymbolAddress((void**)&scoresH,  g_scoresH);
    cudaGetSymbolAddress((void**)&resultrH, g_resultrH);
    cudaGetSymbolAddress((void**)&wtH,      g_wtH);
    cudaGetSymbolAddress((void**)&w1T,      g_w1T);
    cudaGetSymbolAddress((void**)&pp,       g_pp);
    cudaGetSymbolAddress((void**)&invn,     g_invn);

    constexpr int SMEM = 3 * (128 * 72 + 128 * 72) * 2;  // 110592 B (max of modes)
    cudaFuncSetAttribute(gemm_h<3, 0, 0>, cudaFuncAttributeMaxDynamicSharedMemorySize, SMEM);
    cudaFuncSetAttribute(gemm_h<1, 0, 1>, cudaFuncAttributeMaxDynamicSharedMemorySize, SMEM);
    cudaFuncSetAttribute(gemm_h<2, 1, 1>, cudaFuncAttributeMaxDynamicSharedMemorySize, SMEM);
    cudaFuncSetAttribute(gemm_h<2, 1, 2>, cudaFuncAttributeMaxDynamicSharedMemorySize, SMEM);
    cudaFuncSetAttribute(gemm_h<0, 3, 0>, cudaFuncAttributeMaxDynamicSharedMemorySize, SMEM);

    // setup: fp16 operands
    round_half<<<1024, 256>>>(inputs, inrH, BB * LL * DD);
    wtrans_kernel<<<512, 256>>>(conv_w);
    w1trans_kernel<<<dim3(DD / 32, DD / 32), dim3(32, 8)>>>(pool_w1);

    // ---- hop 0: raw similarity on inputs (symmetric split-K2) ----
    gemm_h<3, 0, 0><<<dim3(10, 2, BB), 256, SMEM>>>(
        inrH, inrH, scores, (__half*)scores2, nullptr, nullptr, nullptr, nullptr,
        DD, DD, DD, LL, (long)LL * DD, (long)LL * DD, (long)LL * LL);
    softmask_kernel<<<BB * LL / 8, 256>>>(scores, scores2, scoresH, mask, nullptr);
    gemm_h<1, 0, 1><<<dim3(DD / 128, LL / 128, BB), 256, SMEM>>>(
        scoresH, inrH, nullptr, resultrH, nullptr, nullptr, nullptr, nullptr,
        LL, LL, DD, NH * DD, (long)LL * LL, (long)LL * DD, (long)LL * NH * DD);

    // ---- hops 1..3 ----
    const __half* curH = inrH;   // token-major fp16 current sequence
    for (int h = 0; h < HOPS; h++) {
        __half* crDst = (h & 1) ? convrH1 : convrH0;
        if (h == HOPS - 1) {
            gemm_h<2, 1, 2><<<dim3(DD / 128, LL / 128, BB), 256, SMEM>>>(
                curH, wtH + (long)h * DD * 3 * DD, out, nullptr, crDst,
                conv_b + h * DD, nullptr, nullptr,
                3 * DD, 0, 3 * DD, DD, (long)LL * DD, 0L, (long)LL * DD);
        } else {
            gemm_h<2, 1, 1><<<dim3(DD / 128, LL / 128, BB), 256, SMEM>>>(
                curH, wtH + (long)h * DD * 3 * DD, nullptr, crDst, nullptr,
                conv_b + h * DD, nullptr, nullptr,
                3 * DD, 0, 3 * DD, DD, (long)LL * DD, 0L, (long)LL * DD);
        }
        // raw Gram matrix on un-normalized conv (symmetric, split-K2)
        gemm_h<3, 0, 0><<<dim3(10, 2, BB), 256, SMEM>>>(
            crDst, crDst, scores, (__half*)scores2, nullptr, nullptr, nullptr, nullptr,
            DD, DD, DD, LL, (long)LL * DD, (long)LL * DD, (long)LL * LL);
        // row norms from the Gram diagonal
        diag_kernel<<<(BB * LL + 255) / 256, 256>>>(scores, scores2, invn);
        softmask_kernel<<<BB * LL / 8, 256>>>(scores, scores2, scoresH, mask, invn);
        gemm_h<1, 0, 1><<<dim3(DD / 128, LL / 128, BB), 256, SMEM>>>(
            scoresH, crDst, nullptr, resultrH + (long)(h + 1) * DD, nullptr,
            nullptr, nullptr, nullptr,
            LL, LL, DD, NH * DD, (long)LL * LL, (long)LL * DD, (long)LL * NH * DD);
        curH = crDst;
    }

    // pooling: fused tanh(result@W1+b1)·w2 partials
    gemm_h<0, 3, 0><<<dim3(DD / 128, (BB * LL * NH) / 128, 1), 256, SMEM>>>(
        resultrH, w1T, nullptr, nullptr, nullptr, pool_b1, pool_w2, pp,
        DD, DD, DD, DD, 0L, 0L, 0L);

    // output #2: weighted
    pool_finalize_kernel<<<BB * LL / 8, 256>>>(pool_b2, out + (long)BB * LL * DD);
}